// round 6
// baseline (speedup 1.0000x reference)
#include <cuda_runtime.h>
#include <math_constants.h>
#include <stdint.h>
#include <limits.h>

#define NROWS  32768
#define DIM    256
#define KCODES 8192

#define BM 128
#define BN 128
#define NTILES (KCODES / BN)   // 64
#define NPACK  (DIM / 4)       // 64 packed k-chunks
#define WINDOW_INT 8192
#define SXQ 12.7f
#define SWQ 1040384.0f         // 127 * 8192

#define SST 132                // smem row stride in uint32 (%4==0, conflict-free)
#define XS_OFF 0
#define XS_SZ  (NPACK * SST * 4)          // 33792 B
#define WS_OFF XS_SZ
#define WS_SZ  (NPACK * SST * 4)          // 33792 B
#define SMEM_TOTAL (XS_SZ + WS_SZ)        // 67584 B

// merge area reuses all smem after the main loop
#define CAND_OFF     0                    // 128 rows * 16 writers * 3 ents * 8B = 49152
#define OVF_LIST_OFF 49152
#define OVF_CNT_OFF  (OVF_LIST_OFF + 128 * 4)

__device__ float g_a[NROWS];
__device__ float g_c[KCODES];
__device__ int   g_idx[NROWS];
__device__ __align__(16) signed char g_x8[NROWS * DIM];
__device__ __align__(16) signed char g_w8[KCODES * DIM];

__device__ __forceinline__ uint32_t pack4(float a, float b, float c, float d, float sc) {
    int i0 = __float2int_rn(fminf(fmaxf(a * sc, -127.f), 127.f));
    int i1 = __float2int_rn(fminf(fmaxf(b * sc, -127.f), 127.f));
    int i2 = __float2int_rn(fminf(fmaxf(c * sc, -127.f), 127.f));
    int i3 = __float2int_rn(fminf(fmaxf(d * sc, -127.f), 127.f));
    return (uint32_t)(i0 & 0xff) | ((uint32_t)(i1 & 0xff) << 8) |
           ((uint32_t)(i2 & 0xff) << 16) | ((uint32_t)(i3 & 0xff) << 24);
}

// ---------------- prep kernels (sumsq + int8 quantize) ----------------
__global__ void vq_prep_x(const float* __restrict__ x, float* __restrict__ a,
                          signed char* __restrict__ x8) {
    int warp = (blockIdx.x * blockDim.x + threadIdx.x) >> 5;
    int lane = threadIdx.x & 31;
    if (warp >= NROWS) return;
    const float4* r4 = (const float4*)(x + (size_t)warp * DIM);
    float4 v0 = r4[lane * 2 + 0], v1 = r4[lane * 2 + 1];
    float s = 0.f;
    s = fmaf(v0.x, v0.x, s); s = fmaf(v0.y, v0.y, s); s = fmaf(v0.z, v0.z, s); s = fmaf(v0.w, v0.w, s);
    s = fmaf(v1.x, v1.x, s); s = fmaf(v1.y, v1.y, s); s = fmaf(v1.z, v1.z, s); s = fmaf(v1.w, v1.w, s);
    #pragma unroll
    for (int o = 16; o; o >>= 1) s += __shfl_xor_sync(0xffffffffu, s, o);
    if (lane == 0) a[warp] = s;
    uint2 p;
    p.x = pack4(v0.x, v0.y, v0.z, v0.w, SXQ);
    p.y = pack4(v1.x, v1.y, v1.z, v1.w, SXQ);
    ((uint2*)(x8 + (size_t)warp * DIM))[lane] = p;
}
__global__ void vq_prep_w(const float* __restrict__ w, float* __restrict__ c,
                          signed char* __restrict__ w8) {
    int warp = (blockIdx.x * blockDim.x + threadIdx.x) >> 5;
    int lane = threadIdx.x & 31;
    if (warp >= KCODES) return;
    const float4* r4 = (const float4*)(w + (size_t)warp * DIM);
    float4 v0 = r4[lane * 2 + 0], v1 = r4[lane * 2 + 1];
    float s = 0.f;
    s = fmaf(v0.x, v0.x, s); s = fmaf(v0.y, v0.y, s); s = fmaf(v0.z, v0.z, s); s = fmaf(v0.w, v0.w, s);
    s = fmaf(v1.x, v1.x, s); s = fmaf(v1.y, v1.y, s); s = fmaf(v1.z, v1.z, s); s = fmaf(v1.w, v1.w, s);
    #pragma unroll
    for (int o = 16; o; o >>= 1) s += __shfl_xor_sync(0xffffffffu, s, o);
    if (lane == 0) c[warp] = s;
    uint2 p;
    p.x = pack4(v0.x, v0.y, v0.z, v0.w, SWQ);
    p.y = pack4(v1.x, v1.y, v1.z, v1.w, SWQ);
    ((uint2*)(w8 + (size_t)warp * DIM))[lane] = p;
}

// ---------------- screen kernel (DP4A SIMT GEMM) ----------------
__global__ __launch_bounds__(256, 2)
void vq_screen(const float* __restrict__ X, const float* __restrict__ W,
               const signed char* __restrict__ X8, const signed char* __restrict__ W8) {
    extern __shared__ char smem[];
    uint32_t* xs = (uint32_t*)(smem + XS_OFF);   // [NPACK][SST]
    uint32_t* ws = (uint32_t*)(smem + WS_OFF);   // [NPACK][SST]

    const int tid = threadIdx.x;
    const int tx = tid & 15;        // code-group
    const int ty = tid >> 4;        // row-group
    const int wid = tid >> 5, lane = tid & 31;
    const int rBase = blockIdx.x * BM;

    // ---- load X tile (128 rows x 64 uint32), transposed into smem ----
    #pragma unroll
    for (int i = 0; i < 8; i++) {
        int idx = tid + i * 256;               // 0..2047
        int row = idx >> 4, q = idx & 15;      // q: uint4 chunk (4 packs)
        uint4 v = *(const uint4*)(X8 + (size_t)(rBase + row) * DIM + q * 16);
        xs[(q * 4 + 0) * SST + row] = v.x;
        xs[(q * 4 + 1) * SST + row] = v.y;
        xs[(q * 4 + 2) * SST + row] = v.z;
        xs[(q * 4 + 3) * SST + row] = v.w;
    }

    // per-(thread,row-slot) running top-2 + max-of-rest
    int v1[8], v2[8], v3[8], k1[8], k2[8];
    #pragma unroll
    for (int i = 0; i < 8; i++) { v1[i] = v2[i] = v3[i] = INT_MIN; k1[i] = k2[i] = 0; }

    for (int nt = 0; nt < NTILES; nt++) {
        // ---- load + transpose W tile ----
        __syncthreads();   // previous tile's reads done
        #pragma unroll
        for (int i = 0; i < 8; i++) {
            int idx = tid + i * 256;
            int row = idx >> 4, q = idx & 15;
            uint4 v = *(const uint4*)(W8 + (size_t)(nt * BN + row) * DIM + q * 16);
            ws[(q * 4 + 0) * SST + row] = v.x;
            ws[(q * 4 + 1) * SST + row] = v.y;
            ws[(q * 4 + 2) * SST + row] = v.z;
            ws[(q * 4 + 3) * SST + row] = v.w;
        }
        __syncthreads();

        int acc[8][8];
        #pragma unroll
        for (int i = 0; i < 8; i++)
            #pragma unroll
            for (int j = 0; j < 8; j++) acc[i][j] = 0;

        #pragma unroll 4
        for (int kk = 0; kk < NPACK; kk++) {
            uint4 xa = *(const uint4*)&xs[kk * SST + ty * 4];
            uint4 xb = *(const uint4*)&xs[kk * SST + 64 + ty * 4];
            uint4 wa = *(const uint4*)&ws[kk * SST + tx * 4];
            uint4 wb = *(const uint4*)&ws[kk * SST + 64 + tx * 4];
            int xf[8] = {(int)xa.x, (int)xa.y, (int)xa.z, (int)xa.w,
                         (int)xb.x, (int)xb.y, (int)xb.z, (int)xb.w};
            int wf[8] = {(int)wa.x, (int)wa.y, (int)wa.z, (int)wa.w,
                         (int)wb.x, (int)wb.y, (int)wb.z, (int)wb.w};
            #pragma unroll
            for (int i = 0; i < 8; i++)
                #pragma unroll
                for (int j = 0; j < 8; j++)
                    acc[i][j] = __dp4a(xf[i], wf[j], acc[i][j]);
        }

        // ---- per-row top-2 (+rest-max) update ----
        #pragma unroll
        for (int i = 0; i < 8; i++) {
            int tm = max(max(max(acc[i][0], acc[i][1]), max(acc[i][2], acc[i][3])),
                         max(max(acc[i][4], acc[i][5]), max(acc[i][6], acc[i][7])));
            if (tm <= v2[i]) {
                v3[i] = max(v3[i], tm);
            } else {
                #pragma unroll
                for (int j = 0; j < 8; j++) {
                    int v = acc[i][j];
                    int kk = nt * BN + ((j < 4) ? (tx * 4 + j) : (64 + tx * 4 + (j - 4)));
                    if (v > v1[i]) {
                        v3[i] = max(v3[i], v2[i]);
                        v2[i] = v1[i]; k2[i] = k1[i];
                        v1[i] = v;     k1[i] = kk;
                    } else if (v > v2[i]) {
                        v3[i] = max(v3[i], v2[i]);
                        v2[i] = v;     k2[i] = kk;
                    } else {
                        v3[i] = max(v3[i], v);
                    }
                }
            }
        }
    }
    __syncthreads();

    // ---- merge candidates into smem (xs/ws dead) ----
    int2* cand = (int2*)(smem + CAND_OFF);     // [row][writer=tx][3]
    int* ovf_list = (int*)(smem + OVF_LIST_OFF);
    int* ovf_cnt  = (int*)(smem + OVF_CNT_OFF);
    #pragma unroll
    for (int i = 0; i < 8; i++) {
        int row = (i < 4) ? (ty * 4 + i) : (64 + ty * 4 + (i - 4));
        int2* p = cand + ((size_t)row * 16 + tx) * 3;
        p[0] = make_int2(v1[i], k1[i]);
        p[1] = make_int2(v2[i], k2[i]);
        p[2] = make_int2(v3[i], -1);
    }
    if (tid == 0) *ovf_cnt = 0;
    __syncthreads();

    // ---- per-row selection (one thread per row) ----
    if (tid < BM) {
        const int row = tid;
        const int2* p = cand + (size_t)row * 48;
        int rowmax = INT_MIN;
        for (int e = 0; e < 48; e++) rowmax = max(rowmax, p[e].x);
        const int th = rowmax - WINDOW_INT;
        int sk[32]; int ns = 0; bool ovf = false;
        for (int e = 0; e < 48; e++) {
            if (p[e].x >= th) {
                int k = p[e].y;
                if (k < 0) ovf = true;
                else if (ns < 32) sk[ns++] = k;
                else ovf = true;
            }
        }
        if (ovf) {
            int pos = atomicAdd(ovf_cnt, 1);
            ovf_list[pos] = row;
        } else {
            const int grow = rBase + row;
            int result = sk[0];
            if (ns > 1) {
                const float arow = g_a[grow];
                const float* xr = X + (size_t)grow * DIM;
                float best = CUDART_INF_F; int bestk = 0x7fffffff;
                for (int i = 0; i < ns; i++) {
                    int k = sk[i];
                    const float* wrp = W + (size_t)k * DIM;
                    float dot = 0.f;
                    #pragma unroll 8
                    for (int d = 0; d < DIM; d++) dot = fmaf(xr[d], wrp[d], dot);
                    float dist = fmaf(-2.f, dot, arow + g_c[k]);
                    if (dist < best || (dist == best && k < bestk)) { best = dist; bestk = k; }
                }
                result = bestk;
            }
            g_idx[grow] = result;
        }
    }
    __syncthreads();

    // ---- overflow rows (rare): exact full recheck, one warp per row ----
    int cnt = *ovf_cnt;
    for (int oi = wid; oi < cnt; oi += 8) {
        int row = ovf_list[oi];
        int grow = rBase + row;
        const float* xr = X + (size_t)grow * DIM;
        float arow = g_a[grow];
        float best = CUDART_INF_F; int bestk = 0x7fffffff;
        for (int kb = lane * 4; kb < KCODES; kb += 128) {
            const float* w0 = W + (size_t)(kb + 0) * DIM;
            const float* w1 = W + (size_t)(kb + 1) * DIM;
            const float* w2 = W + (size_t)(kb + 2) * DIM;
            const float* w3 = W + (size_t)(kb + 3) * DIM;
            float d0 = 0.f, d1 = 0.f, d2 = 0.f, d3 = 0.f;
            for (int d = 0; d < DIM; d++) {
                float xv = xr[d];
                d0 = fmaf(xv, w0[d], d0); d1 = fmaf(xv, w1[d], d1);
                d2 = fmaf(xv, w2[d], d2); d3 = fmaf(xv, w3[d], d3);
            }
            float dd[4];
            dd[0] = fmaf(-2.f, d0, arow + g_c[kb + 0]);
            dd[1] = fmaf(-2.f, d1, arow + g_c[kb + 1]);
            dd[2] = fmaf(-2.f, d2, arow + g_c[kb + 2]);
            dd[3] = fmaf(-2.f, d3, arow + g_c[kb + 3]);
            #pragma unroll
            for (int c = 0; c < 4; c++)
                if (dd[c] < best || (dd[c] == best && (kb + c) < bestk)) { best = dd[c]; bestk = kb + c; }
        }
        #pragma unroll
        for (int off = 16; off; off >>= 1) {
            float ob = __shfl_xor_sync(0xffffffffu, best, off);
            int   ok = __shfl_xor_sync(0xffffffffu, bestk, off);
            if (ob < best || (ob == best && ok < bestk)) { best = ob; bestk = ok; }
        }
        if (lane == 0) g_idx[grow] = bestk;
    }
}

// ---------------- gather ----------------
__global__ void vq_gather_kernel(const float* __restrict__ W,
                                 float* __restrict__ out,
                                 float* __restrict__ out_idx) {
    int warp = (blockIdx.x * blockDim.x + threadIdx.x) >> 5;
    int lane = threadIdx.x & 31;
    if (warp >= NROWS) return;
    int k = g_idx[warp];
    const float4* src = (const float4*)(W + (size_t)k * DIM);
    float4* dst = (float4*)(out + (size_t)warp * DIM);
    dst[lane]      = src[lane];
    dst[lane + 32] = src[lane + 32];
    if (out_idx != nullptr && lane == 0) out_idx[warp] = (float)k;
}

// ---------------- launcher ----------------
extern "C" void kernel_launch(void* const* d_in, const int* in_sizes, int n_in,
                              void* d_out, int out_size) {
    const float* X = (const float*)d_in[0];
    const float* W = (const float*)d_in[1];
    if (n_in >= 2 && in_sizes[0] == KCODES * DIM && in_sizes[1] == NROWS * DIM) {
        W = (const float*)d_in[0];
        X = (const float*)d_in[1];
    }
    float* out = (float*)d_out;

    float* pa = nullptr; float* pc = nullptr;
    signed char* px8 = nullptr; signed char* pw8 = nullptr;
    cudaGetSymbolAddress((void**)&pa, g_a);
    cudaGetSymbolAddress((void**)&pc, g_c);
    cudaGetSymbolAddress((void**)&px8, g_x8);
    cudaGetSymbolAddress((void**)&pw8, g_w8);

    cudaFuncSetAttribute(vq_screen, cudaFuncAttributeMaxDynamicSharedMemorySize, SMEM_TOTAL);

    vq_prep_x<<<NROWS / 8, 256>>>(X, pa, px8);
    vq_prep_w<<<KCODES / 8, 256>>>(W, pc, pw8);
    vq_screen<<<NROWS / BM, 256, SMEM_TOTAL>>>(X, W, px8, pw8);

    float* out_idx = (out_size >= NROWS * DIM + NROWS) ? (out + (size_t)NROWS * DIM) : nullptr;
    vq_gather_kernel<<<NROWS / 8, 256>>>(W, out, out_idx);
}

// round 7
// speedup vs baseline: 15.6879x; 15.6879x over previous
#include <cuda_runtime.h>
#include <cuda_fp16.h>
#include <math_constants.h>
#include <stdint.h>

#define NROWS  32768
#define DIM    256
#define KCODES 8192

#define BM 128
#define BN 128
#define NTILES (KCODES / BN)   // 64
#define WINDOW 0.75f           // scaled-dot domain (dot * 4096)

#define ASTRIDE 528            // 256 f16 = 512B + 16B pad (conflict-free ldmatrix)
#define A_OFF 0
#define A_SZ  (BM * ASTRIDE)               // 67584
#define B_OFF A_SZ
#define B_SZ  (BN * ASTRIDE)               // 67584
#define SMEM_TOTAL (A_SZ + 2 * B_SZ)       // 202752

// candidate-merge area reuses the (dead) B-buffer region after the main loop
#define CAND_OFF     B_OFF                  // 128 rows * 16 writers * 3 ents * 8B = 49152
#define OVF_LIST_OFF (B_OFF + 49152)
#define OVF_CNT_OFF  (OVF_LIST_OFF + 128 * 4)

__device__ float  g_a[NROWS];
__device__ float  g_c[KCODES];
__device__ int    g_idx[NROWS];
__device__ __align__(16) __half g_xh[NROWS * DIM];
__device__ __align__(16) __half g_wh[KCODES * DIM];   // W * 4096

// ---------------- asm helpers ----------------
__device__ __forceinline__ uint32_t smem_u32(const void* p) {
    uint32_t a;
    asm("{ .reg .u64 t; cvta.to.shared.u64 t, %1; cvt.u32.u64 %0, t; }" : "=r"(a) : "l"(p));
    return a;
}
__device__ __forceinline__ void cp16(uint32_t s, const void* g) {
    asm volatile("cp.async.cg.shared.global [%0], [%1], 16;" :: "r"(s), "l"(g));
}
#define CP_COMMIT() asm volatile("cp.async.commit_group;" ::: "memory")
#define CP_WAIT0()  asm volatile("cp.async.wait_group 0;" ::: "memory")

__device__ __forceinline__ void ldsm4(uint32_t addr, uint32_t& r0, uint32_t& r1,
                                      uint32_t& r2, uint32_t& r3) {
    asm volatile("ldmatrix.sync.aligned.m8n8.x4.shared.b16 {%0,%1,%2,%3}, [%4];"
                 : "=r"(r0), "=r"(r1), "=r"(r2), "=r"(r3) : "r"(addr));
}
__device__ __forceinline__ void mma16816(float* c, const uint32_t* a, const uint32_t* b) {
    asm volatile(
        "mma.sync.aligned.m16n8k16.row.col.f32.f16.f16.f32 "
        "{%0,%1,%2,%3}, {%4,%5,%6,%7}, {%8,%9}, {%0,%1,%2,%3};"
        : "+f"(c[0]), "+f"(c[1]), "+f"(c[2]), "+f"(c[3])
        : "r"(a[0]), "r"(a[1]), "r"(a[2]), "r"(a[3]), "r"(b[0]), "r"(b[1]));
}

// ---------------- prep kernels ----------------
__global__ void vq_prep_x(const float* __restrict__ x, float* __restrict__ a,
                          __half* __restrict__ xh) {
    int warp = (blockIdx.x * blockDim.x + threadIdx.x) >> 5;
    int lane = threadIdx.x & 31;
    if (warp >= NROWS) return;
    const float4* r4 = (const float4*)(x + (size_t)warp * DIM);
    float4 v0 = r4[lane * 2 + 0], v1 = r4[lane * 2 + 1];
    float s = 0.f;
    s = fmaf(v0.x, v0.x, s); s = fmaf(v0.y, v0.y, s); s = fmaf(v0.z, v0.z, s); s = fmaf(v0.w, v0.w, s);
    s = fmaf(v1.x, v1.x, s); s = fmaf(v1.y, v1.y, s); s = fmaf(v1.z, v1.z, s); s = fmaf(v1.w, v1.w, s);
    #pragma unroll
    for (int o = 16; o; o >>= 1) s += __shfl_xor_sync(0xffffffffu, s, o);
    if (lane == 0) a[warp] = s;
    __half2 h0 = __floats2half2_rn(v0.x, v0.y), h1 = __floats2half2_rn(v0.z, v0.w);
    __half2 h2 = __floats2half2_rn(v1.x, v1.y), h3 = __floats2half2_rn(v1.z, v1.w);
    uint4 u;
    u.x = *(unsigned*)&h0; u.y = *(unsigned*)&h1; u.z = *(unsigned*)&h2; u.w = *(unsigned*)&h3;
    ((uint4*)(xh + (size_t)warp * DIM))[lane] = u;
}
__global__ void vq_prep_w(const float* __restrict__ w, float* __restrict__ c,
                          __half* __restrict__ wh) {
    int warp = (blockIdx.x * blockDim.x + threadIdx.x) >> 5;
    int lane = threadIdx.x & 31;
    if (warp >= KCODES) return;
    const float4* r4 = (const float4*)(w + (size_t)warp * DIM);
    float4 v0 = r4[lane * 2 + 0], v1 = r4[lane * 2 + 1];
    float s = 0.f;
    s = fmaf(v0.x, v0.x, s); s = fmaf(v0.y, v0.y, s); s = fmaf(v0.z, v0.z, s); s = fmaf(v0.w, v0.w, s);
    s = fmaf(v1.x, v1.x, s); s = fmaf(v1.y, v1.y, s); s = fmaf(v1.z, v1.z, s); s = fmaf(v1.w, v1.w, s);
    #pragma unroll
    for (int o = 16; o; o >>= 1) s += __shfl_xor_sync(0xffffffffu, s, o);
    if (lane == 0) c[warp] = s;
    const float SC = 4096.0f;
    __half2 h0 = __floats2half2_rn(v0.x * SC, v0.y * SC), h1 = __floats2half2_rn(v0.z * SC, v0.w * SC);
    __half2 h2 = __floats2half2_rn(v1.x * SC, v1.y * SC), h3 = __floats2half2_rn(v1.z * SC, v1.w * SC);
    uint4 u;
    u.x = *(unsigned*)&h0; u.y = *(unsigned*)&h1; u.z = *(unsigned*)&h2; u.w = *(unsigned*)&h3;
    ((uint4*)(wh + (size_t)warp * DIM))[lane] = u;
}

// ---------------- screen kernel (HMMA, 16 warps / 4 per SMSP) ----------------
__global__ __launch_bounds__(512, 1)
void vq_screen(const float* __restrict__ X, const float* __restrict__ W,
               const __half* __restrict__ Xh, const __half* __restrict__ Wh) {
    extern __shared__ char smem[];
    const uint32_t sb = smem_u32(smem);
    const int tid = threadIdx.x;
    const int wid = tid >> 5, lane = tid & 31;
    const int warp_m = wid >> 2, warp_n = wid & 3;   // 4x4 warp grid: 32x32 tiles
    const int g = lane >> 2, t = lane & 3;
    const int rBase = blockIdx.x * BM;

    // ---- prologue: A tile + B tile 0 via cp.async ----
    #pragma unroll
    for (int i = 0; i < 8; i++) {
        int idx = tid + i * 512;               // 0..4095
        int row = idx >> 5, c = idx & 31;
        cp16(sb + A_OFF + row * ASTRIDE + c * 16,
             Xh + (size_t)(rBase + row) * DIM + c * 8);
    }
    #pragma unroll
    for (int i = 0; i < 8; i++) {
        int idx = tid + i * 512;
        int row = idx >> 5, c = idx & 31;
        cp16(sb + B_OFF + row * ASTRIDE + c * 16,
             Wh + (size_t)row * DIM + c * 8);
    }
    CP_COMMIT();

    // per-(lane,slot) top-2 + rest-max; slot s = mi*2 + h (4 slots)
    float cv1[4], cv2[4], cv3[4];
    int   ck1[4], ck2[4];
    #pragma unroll
    for (int s = 0; s < 4; s++) {
        cv1[s] = cv2[s] = cv3[s] = -CUDART_INF_F;
        ck1[s] = ck2[s] = 0;
    }

    // ldmatrix base addresses (identical mapping to round-4 proven kernel)
    const uint32_t a_base = sb + A_OFF +
        (uint32_t)(warp_m * 32 + (lane & 15)) * ASTRIDE + (uint32_t)(lane >> 4) * 16;
    const uint32_t b_row_off =
        (uint32_t)(warp_n * 32 + (lane & 7) + (lane >> 4) * 8) * ASTRIDE +
        (uint32_t)((lane >> 3) & 1) * 16;

    for (int nt = 0; nt < NTILES; nt++) {
        CP_WAIT0();
        __syncthreads();
        if (nt + 1 < NTILES) {
            int buf = (nt + 1) & 1;
            #pragma unroll
            for (int i = 0; i < 8; i++) {
                int idx = tid + i * 512;
                int row = idx >> 5, c = idx & 31;
                cp16(sb + B_OFF + buf * B_SZ + row * ASTRIDE + c * 16,
                     Wh + (size_t)((nt + 1) * BN + row) * DIM + c * 8);
            }
            CP_COMMIT();
        }

        // ---- GEMM: 32x32 warp tile over K=256 ----
        float acc[2][4][4];
        #pragma unroll
        for (int mi = 0; mi < 2; mi++)
            #pragma unroll
            for (int ni = 0; ni < 4; ni++)
                #pragma unroll
                for (int c = 0; c < 4; c++) acc[mi][ni][c] = 0.f;

        const uint32_t b_base = sb + B_OFF + (uint32_t)(nt & 1) * B_SZ + b_row_off;
        #pragma unroll 4
        for (int ks = 0; ks < 16; ks++) {
            uint32_t af[2][4], bf[4][2];
            #pragma unroll
            for (int mi = 0; mi < 2; mi++)
                ldsm4(a_base + (uint32_t)mi * 16 * ASTRIDE + (uint32_t)ks * 32,
                      af[mi][0], af[mi][1], af[mi][2], af[mi][3]);
            ldsm4(b_base + (uint32_t)ks * 32, bf[0][0], bf[0][1], bf[1][0], bf[1][1]);
            ldsm4(b_base + 16u * ASTRIDE + (uint32_t)ks * 32,
                  bf[2][0], bf[2][1], bf[3][0], bf[3][1]);
            #pragma unroll
            for (int mi = 0; mi < 2; mi++)
                #pragma unroll
                for (int ni = 0; ni < 4; ni++)
                    mma16816(acc[mi][ni], af[mi], bf[ni]);
        }

        // ---- epilogue: per-slot top-2 + rest-max update ----
        #pragma unroll
        for (int mi = 0; mi < 2; mi++) {
            #pragma unroll
            for (int h = 0; h < 2; h++) {
                const int s = mi * 2 + h;
                float tm = fmaxf(fmaxf(fmaxf(acc[mi][0][2*h], acc[mi][0][2*h+1]),
                                       fmaxf(acc[mi][1][2*h], acc[mi][1][2*h+1])),
                                 fmaxf(fmaxf(acc[mi][2][2*h], acc[mi][2][2*h+1]),
                                       fmaxf(acc[mi][3][2*h], acc[mi][3][2*h+1])));
                if (tm <= cv2[s]) {
                    cv3[s] = fmaxf(cv3[s], tm);
                } else {
                    #pragma unroll
                    for (int ni = 0; ni < 4; ni++) {
                        #pragma unroll
                        for (int c = 0; c < 2; c++) {
                            float v = acc[mi][ni][2 * h + c];
                            int kk = nt * BN + warp_n * 32 + ni * 8 + 2 * t + c;
                            if (v > cv1[s]) {
                                cv3[s] = fmaxf(cv3[s], cv2[s]);
                                cv2[s] = cv1[s]; ck2[s] = ck1[s];
                                cv1[s] = v;      ck1[s] = kk;
                            } else if (v > cv2[s]) {
                                cv3[s] = fmaxf(cv3[s], cv2[s]);
                                cv2[s] = v;      ck2[s] = kk;
                            } else {
                                cv3[s] = fmaxf(cv3[s], v);
                            }
                        }
                    }
                }
            }
        }
        __syncthreads();
    }

    // ---- merge: write candidates to smem (B buffers dead) ----
    float2* cand = (float2*)(smem + CAND_OFF);
    int* ovf_list = (int*)(smem + OVF_LIST_OFF);
    int* ovf_cnt  = (int*)(smem + OVF_CNT_OFF);
    const int wr = warp_n * 4 + t;   // 16 writers per row
    #pragma unroll
    for (int mi = 0; mi < 2; mi++) {
        #pragma unroll
        for (int h = 0; h < 2; h++) {
            const int s = mi * 2 + h;
            int row = warp_m * 32 + mi * 16 + h * 8 + g;
            float2* p = cand + ((size_t)row * 16 + wr) * 3;
            p[0] = make_float2(cv1[s], __int_as_float(ck1[s]));
            p[1] = make_float2(cv2[s], __int_as_float(ck2[s]));
            p[2] = make_float2(cv3[s], __int_as_float(-1));
        }
    }
    if (tid == 0) *ovf_cnt = 0;
    __syncthreads();

    // ---- per-row selection (one thread per row) ----
    if (tid < BM) {
        const int row = tid;
        const float2* p = cand + (size_t)row * 48;
        float rowmax = -CUDART_INF_F;
        for (int e = 0; e < 48; e++) rowmax = fmaxf(rowmax, p[e].x);
        const float th = rowmax - WINDOW;
        int sk[16]; int ns = 0; bool ovf = false;
        for (int e = 0; e < 48; e++) {
            if (p[e].x >= th) {
                int k = __float_as_int(p[e].y);
                if (k < 0) ovf = true;
                else if (ns < 16) sk[ns++] = k;
                else ovf = true;
            }
        }
        if (ovf) {
            int pos = atomicAdd(ovf_cnt, 1);
            ovf_list[pos] = row;
        } else {
            const int grow = rBase + row;
            int result = sk[0];
            if (ns > 1) {
                const float arow = g_a[grow];
                const float* xr = X + (size_t)grow * DIM;
                float best = CUDART_INF_F; int bestk = 0x7fffffff;
                for (int i = 0; i < ns; i++) {
                    int k = sk[i];
                    const float* wrp = W + (size_t)k * DIM;
                    float dot = 0.f;
                    #pragma unroll 8
                    for (int d = 0; d < DIM; d++) dot = fmaf(xr[d], wrp[d], dot);
                    float dist = fmaf(-2.f, dot, arow + g_c[k]);
                    if (dist < best || (dist == best && k < bestk)) { best = dist; bestk = k; }
                }
                result = bestk;
            }
            g_idx[grow] = result;
        }
    }
    __syncthreads();

    // ---- overflow rows (rare): full exact recheck, one warp per row ----
    int cnt = *ovf_cnt;
    for (int oi = wid; oi < cnt; oi += 16) {
        int row = ovf_list[oi];
        int grow = rBase + row;
        const float* xr = X + (size_t)grow * DIM;
        float arow = g_a[grow];
        float best = CUDART_INF_F; int bestk = 0x7fffffff;
        for (int kb = lane * 4; kb < KCODES; kb += 128) {
            const float* w0 = W + (size_t)(kb + 0) * DIM;
            const float* w1 = W + (size_t)(kb + 1) * DIM;
            const float* w2 = W + (size_t)(kb + 2) * DIM;
            const float* w3 = W + (size_t)(kb + 3) * DIM;
            float d0 = 0.f, d1 = 0.f, d2 = 0.f, d3 = 0.f;
            for (int d = 0; d < DIM; d++) {
                float xv = xr[d];
                d0 = fmaf(xv, w0[d], d0); d1 = fmaf(xv, w1[d], d1);
                d2 = fmaf(xv, w2[d], d2); d3 = fmaf(xv, w3[d], d3);
            }
            float dd[4];
            dd[0] = fmaf(-2.f, d0, arow + g_c[kb + 0]);
            dd[1] = fmaf(-2.f, d1, arow + g_c[kb + 1]);
            dd[2] = fmaf(-2.f, d2, arow + g_c[kb + 2]);
            dd[3] = fmaf(-2.f, d3, arow + g_c[kb + 3]);
            #pragma unroll
            for (int c = 0; c < 4; c++)
                if (dd[c] < best || (dd[c] == best && (kb + c) < bestk)) { best = dd[c]; bestk = kb + c; }
        }
        #pragma unroll
        for (int off = 16; off; off >>= 1) {
            float ob = __shfl_xor_sync(0xffffffffu, best, off);
            int   ok = __shfl_xor_sync(0xffffffffu, bestk, off);
            if (ob < best || (ob == best && ok < bestk)) { best = ob; bestk = ok; }
        }
        if (lane == 0) g_idx[grow] = bestk;
    }
}

// ---------------- gather ----------------
__global__ void vq_gather_kernel(const float* __restrict__ W,
                                 float* __restrict__ out,
                                 float* __restrict__ out_idx) {
    int warp = (blockIdx.x * blockDim.x + threadIdx.x) >> 5;
    int lane = threadIdx.x & 31;
    if (warp >= NROWS) return;
    int k = g_idx[warp];
    const float4* src = (const float4*)(W + (size_t)k * DIM);
    float4* dst = (float4*)(out + (size_t)warp * DIM);
    dst[lane]      = src[lane];
    dst[lane + 32] = src[lane + 32];
    if (out_idx != nullptr && lane == 0) out_idx[warp] = (float)k;
}

// ---------------- launcher ----------------
extern "C" void kernel_launch(void* const* d_in, const int* in_sizes, int n_in,
                              void* d_out, int out_size) {
    const float* X = (const float*)d_in[0];
    const float* W = (const float*)d_in[1];
    if (n_in >= 2 && in_sizes[0] == KCODES * DIM && in_sizes[1] == NROWS * DIM) {
        W = (const float*)d_in[0];
        X = (const float*)d_in[1];
    }
    float* out = (float*)d_out;

    float* pa = nullptr; float* pc = nullptr;
    __half* pxh = nullptr; __half* pwh = nullptr;
    cudaGetSymbolAddress((void**)&pa, g_a);
    cudaGetSymbolAddress((void**)&pc, g_c);
    cudaGetSymbolAddress((void**)&pxh, g_xh);
    cudaGetSymbolAddress((void**)&pwh, g_wh);

    cudaFuncSetAttribute(vq_screen, cudaFuncAttributeMaxDynamicSharedMemorySize, SMEM_TOTAL);

    vq_prep_x<<<NROWS / 8, 256>>>(X, pa, pxh);
    vq_prep_w<<<KCODES / 8, 256>>>(W, pc, pwh);
    vq_screen<<<NROWS / BM, 512, SMEM_TOTAL>>>(X, W, pxh, pwh);

    float* out_idx = (out_size >= NROWS * DIM + NROWS) ? (out + (size_t)NROWS * DIM) : nullptr;
    vq_gather_kernel<<<NROWS / 8, 256>>>(W, out, out_idx);
}

// round 8
// speedup vs baseline: 27.5235x; 1.7544x over previous
#include <cuda_runtime.h>
#include <math_constants.h>
#include <stdint.h>

// Problem sizes (fixed by the reference)
#define NROWS 32768      // 8 * 4096
#define DIM   256
#define KCODES 8192

// Scratch
__device__ float g_a[NROWS];    // ||x||^2 per input row
__device__ float g_c[KCODES];   // ||w||^2 per code row
__device__ int   g_idx[NROWS];  // argmin indices

// ---------------------------------------------------------------------------
// Kernel 1: per-row sum of squares (one warp per row)
// ---------------------------------------------------------------------------
__global__ void vq_sumsq_kernel(const float* __restrict__ x,
                                float* __restrict__ out, int nrows) {
    int warp = (blockIdx.x * blockDim.x + threadIdx.x) >> 5;
    int lane = threadIdx.x & 31;
    if (warp >= nrows) return;
    const float4* r4 = (const float4*)(x + (size_t)warp * DIM);
    float4 v0 = r4[lane * 2 + 0];
    float4 v1 = r4[lane * 2 + 1];
    float s = 0.f;
    s = fmaf(v0.x, v0.x, s); s = fmaf(v0.y, v0.y, s);
    s = fmaf(v0.z, v0.z, s); s = fmaf(v0.w, v0.w, s);
    s = fmaf(v1.x, v1.x, s); s = fmaf(v1.y, v1.y, s);
    s = fmaf(v1.z, v1.z, s); s = fmaf(v1.w, v1.w, s);
    #pragma unroll
    for (int off = 16; off; off >>= 1)
        s += __shfl_xor_sync(0xffffffffu, s, off);
    if (lane == 0) out[warp] = s;
}

// ---------------------------------------------------------------------------
// Kernel 2: fused distance GEMM + argmin, inner loop on packed fma.rn.f32x2.
//   Identical structure/numerics to the round-1 roofline kernel: each pack
//   half is the same IEEE FMA chain in the same order -> bit-identical dist.
// ---------------------------------------------------------------------------
#define BM 128
#define BN 128
#define BK 16
#define SST 132   // smem row stride (floats), %4==0 for float4/float2 alignment

typedef unsigned long long ull;

__device__ __forceinline__ ull pack2(float lo, float hi) {
    ull r;
    asm("mov.b64 %0, {%1, %2};" : "=l"(r) : "f"(lo), "f"(hi));
    return r;
}
__device__ __forceinline__ void unpack2(ull v, float& lo, float& hi) {
    asm("mov.b64 {%0, %1}, %2;" : "=f"(lo), "=f"(hi) : "l"(v));
}
__device__ __forceinline__ void fma2(ull& d, ull a, ull b) {
    asm("fma.rn.f32x2 %0, %1, %2, %0;" : "+l"(d) : "l"(a), "l"(b));
}

__global__ __launch_bounds__(256, 2)
void vq_argmin_kernel(const float* __restrict__ X, const float* __restrict__ W) {
    __shared__ float xs[BK][SST];
    __shared__ float ws[BK][SST];
    __shared__ float cs[BN];
    __shared__ float rd[BM];
    __shared__ int   rk[BM];

    const int tid = threadIdx.x;
    const int tx = tid & 15;        // code-group  (16)
    const int ty = tid >> 4;        // row-group   (16)
    const int rBase = blockIdx.x * BM;

    // per-thread rows: ty*4 + i (i<4) and 64 + ty*4 + (i-4)
    float a_reg[8];
    #pragma unroll
    for (int i = 0; i < 8; i++) {
        int rl = (i < 4) ? (ty * 4 + i) : (64 + ty * 4 + (i - 4));
        a_reg[i] = g_a[rBase + rl];
    }

    float bestD[8];
    int   bestK[8];
    #pragma unroll
    for (int i = 0; i < 8; i++) { bestD[i] = CUDART_INF_F; bestK[i] = 0x3fffffff; }

    for (int kt = 0; kt < KCODES / BN; kt++) {
        if (tid < BN) cs[tid] = g_c[kt * BN + tid];

        // packed accumulators: acc2[i][jp] holds codes (jp*2, jp*2+1) of the 8
        ull acc2[8][4];
        #pragma unroll
        for (int i = 0; i < 8; i++)
            #pragma unroll
            for (int jp = 0; jp < 4; jp++) acc2[i][jp] = 0ull;

        for (int dc = 0; dc < DIM / BK; dc++) {
            // ---- load 128x16 tiles of X and W, transposed into smem ----
            #pragma unroll
            for (int h = 0; h < 2; h++) {
                int idx = tid + h * 256;       // 0..511
                int row = idx >> 2;            // 0..127
                int seg = idx & 3;             // float4 within the 16 d's
                float4 v = *(const float4*)(X + (size_t)(rBase + row) * DIM + dc * BK + seg * 4);
                xs[seg * 4 + 0][row] = v.x; xs[seg * 4 + 1][row] = v.y;
                xs[seg * 4 + 2][row] = v.z; xs[seg * 4 + 3][row] = v.w;
                float4 u = *(const float4*)(W + (size_t)(kt * BN + row) * DIM + dc * BK + seg * 4);
                ws[seg * 4 + 0][row] = u.x; ws[seg * 4 + 1][row] = u.y;
                ws[seg * 4 + 2][row] = u.z; ws[seg * 4 + 3][row] = u.w;
            }
            __syncthreads();

            #pragma unroll
            for (int d = 0; d < BK; d++) {
                float4 xa = *(const float4*)&xs[d][ty * 4];
                float4 xb = *(const float4*)&xs[d][64 + ty * 4];
                // W pairs: adjacent codes load directly as 64-bit values
                ull wp[4];
                wp[0] = *(const ull*)&ws[d][tx * 4];
                wp[1] = *(const ull*)&ws[d][tx * 4 + 2];
                wp[2] = *(const ull*)&ws[d][64 + tx * 4];
                wp[3] = *(const ull*)&ws[d][64 + tx * 4 + 2];
                ull xp[8];
                xp[0] = pack2(xa.x, xa.x); xp[1] = pack2(xa.y, xa.y);
                xp[2] = pack2(xa.z, xa.z); xp[3] = pack2(xa.w, xa.w);
                xp[4] = pack2(xb.x, xb.x); xp[5] = pack2(xb.y, xb.y);
                xp[6] = pack2(xb.z, xb.z); xp[7] = pack2(xb.w, xb.w);
                #pragma unroll
                for (int i = 0; i < 8; i++)
                    #pragma unroll
                    for (int jp = 0; jp < 4; jp++)
                        fma2(acc2[i][jp], xp[i], wp[jp]);
            }
            __syncthreads();
        }

        // ---- epilogue: distances + running argmin (identical to round 1) ----
        #pragma unroll
        for (int i = 0; i < 8; i++) {
            #pragma unroll
            for (int jp = 0; jp < 4; jp++) {
                float d0, d1;
                unpack2(acc2[i][jp], d0, d1);
                #pragma unroll
                for (int c = 0; c < 2; c++) {
                    int j = jp * 2 + c;
                    int kl = (j < 4) ? (tx * 4 + j) : (64 + tx * 4 + (j - 4));
                    float dotv = (c == 0) ? d0 : d1;
                    float t = a_reg[i] + cs[kl];              // fl(a + c_k)
                    float dist = fmaf(-2.f, dotv, t);         // == fl(t - fl(2*dot))
                    int k = kt * BN + kl;
                    if (dist < bestD[i] || (dist == bestD[i] && k < bestK[i])) {
                        bestD[i] = dist; bestK[i] = k;
                    }
                }
            }
        }
    }

    // ---- cross-thread per-row reduction (lexicographic (d,k): order-safe) ----
    if (tid < BM) { rd[tid] = CUDART_INF_F; rk[tid] = 0x3fffffff; }
    __syncthreads();
    for (int t = 0; t < 16; t++) {
        if (tx == t) {
            #pragma unroll
            for (int i = 0; i < 8; i++) {
                int rl = (i < 4) ? (ty * 4 + i) : (64 + ty * 4 + (i - 4));
                if (bestD[i] < rd[rl] || (bestD[i] == rd[rl] && bestK[i] < rk[rl])) {
                    rd[rl] = bestD[i]; rk[rl] = bestK[i];
                }
            }
        }
        __syncthreads();
    }
    if (tid < BM) g_idx[rBase + tid] = rk[tid];
}

// ---------------------------------------------------------------------------
// Kernel 3: gather W[idx] into output (+ indices as floats, if room)
// ---------------------------------------------------------------------------
__global__ void vq_gather_kernel(const float* __restrict__ W,
                                 float* __restrict__ out,
                                 float* __restrict__ out_idx) {
    int warp = (blockIdx.x * blockDim.x + threadIdx.x) >> 5;
    int lane = threadIdx.x & 31;
    if (warp >= NROWS) return;
    int k = g_idx[warp];
    const float4* src = (const float4*)(W + (size_t)k * DIM);
    float4* dst = (float4*)(out + (size_t)warp * DIM);
    dst[lane]      = src[lane];
    dst[lane + 32] = src[lane + 32];
    if (out_idx != nullptr && lane == 0) out_idx[warp] = (float)k;
}

// ---------------------------------------------------------------------------
extern "C" void kernel_launch(void* const* d_in, const int* in_sizes, int n_in,
                              void* d_out, int out_size) {
    const float* X = (const float*)d_in[0];
    const float* W = (const float*)d_in[1];
    if (n_in >= 2 && in_sizes[0] == KCODES * DIM && in_sizes[1] == NROWS * DIM) {
        W = (const float*)d_in[0];
        X = (const float*)d_in[1];
    }
    float* out = (float*)d_out;

    float* pa = nullptr; float* pc = nullptr;
    cudaGetSymbolAddress((void**)&pa, g_a);
    cudaGetSymbolAddress((void**)&pc, g_c);

    vq_sumsq_kernel<<<NROWS / 8, 256>>>(X, pa, NROWS);
    vq_sumsq_kernel<<<KCODES / 8, 256>>>(W, pc, KCODES);
    vq_argmin_kernel<<<NROWS / BM, 256>>>(X, W);

    float* out_idx = (out_size >= NROWS * DIM + NROWS) ? (out + (size_t)NROWS * DIM)
                                                       : nullptr;
    vq_gather_kernel<<<NROWS / 8, 256>>>(W, out, out_idx);
}